// round 15
// baseline (speedup 1.0000x reference)
#include <cuda_runtime.h>
#include <cuda_bf16.h>

// RandomResizedCrop resample: out[i] = (1-w)*cropped[lo_c] + w*cropped[hi_c],
// idx = f32(i) * delta, delta = f32(crop_len-1)/f32(n-1) (= 0.875f here),
// lo_c/hi_c clamped to crop_len-1 (JAX gather clamp), w from UNclamped
// floor(idx). Matches reference to rel_err 6.9e-9.
//
// R13 shape (35.4us best: 512-thread blocks, lane-consecutive gathers
// MLP~16, evict-last policy reads, __stcs evict-first stores, single
// L2-prefetch stream one resident-set ahead). One change: prefetch
// DISTANCE doubled (592 -> 1184 blocks, ~16.6 MB look-ahead, ~5us) so
// each prefetch has 2x the slack to complete before demand gathers hit
// the line. Same op count (R12 showed a second prefetch stream costs L1;
// this changes only the address). L2-retention avenue closed (R9/R10/R14
// all flat): cyclic 117 MB sweep through 126 MB L2 self-evicts its head
// regardless of policy, so ~68 MB/replay read stream is structural.

#define THREADS      512
#define OUT_PER_THR  8
#define OUT_TILE     (THREADS * OUT_PER_THR)   // 4096 outputs per block
#define PF_AHEAD     1184                      // two resident sets ahead
#define PF_LINES     112                       // 4096*0.875 floats = 112 x 128B
#define WIN_FLOATS   3584                      // OUT_TILE * 7/8

__device__ __forceinline__ unsigned long long make_evict_last_policy() {
    unsigned long long pol;
    asm volatile("createpolicy.fractional.L2::evict_last.b64 %0, 1.0;"
                 : "=l"(pol));
    return pol;
}

__device__ __forceinline__ float ldg_policy(const float* p, unsigned long long pol) {
    float v;
    asm volatile("ld.global.nc.L2::cache_hint.f32 %0, [%1], %2;"
                 : "=f"(v) : "l"(p), "l"(pol));
    return v;
}

__global__ __launch_bounds__(THREADS)
void resample_pfd_kernel(const float* __restrict__ audio,
                         const int* __restrict__ p_crop,
                         const int* __restrict__ p_start,
                         float* __restrict__ out,
                         int n, int audio_len) {
    const int crop_len = __ldg(p_crop);
    const int start    = __ldg(p_start);
    const float delta  = (float)(crop_len - 1) / (float)(n - 1);
    const int clampv   = crop_len - 1;
    const float* __restrict__ base = audio + start;
    const unsigned long long pol = make_evict_last_policy();

    // Single-distance prefetch, two resident-sets ahead.
    if (threadIdx.x < PF_LINES) {
        int b2  = blockIdx.x + PF_AHEAD;
        int pfi = b2 * WIN_FLOATS + (int)threadIdx.x * 32 - 8;  // -8: fp32 slack
        pfi = max(pfi, 0);
        pfi = min(start + pfi, audio_len - 1);
        asm volatile("prefetch.global.L2 [%0];" :: "l"(audio + pfi));
    }

    const int i0 = blockIdx.x * OUT_TILE + threadIdx.x;

    // Phase 1: indices/weights, issue all 16 gathers (independent, MLP~16).
    float a[OUT_PER_THR], b[OUT_PER_THR], w[OUT_PER_THR];
    #pragma unroll
    for (int k = 0; k < OUT_PER_THR; k++) {
        int i      = i0 + k * THREADS;
        float fi   = (float)i;         // RN convert (matches f32 iota rounding)
        float idx  = fi * delta;       // RN multiply (matches XLA linspace)
        int lo     = (int)floorf(idx);
        w[k]       = idx - (float)lo;  // from UNclamped lo (reference semantics)
        int lo_c   = min(lo,     clampv);   // JAX gather clamp
        int hi_c   = min(lo + 1, clampv);
        a[k]       = ldg_policy(base + lo_c, pol);
        b[k]       = ldg_policy(base + hi_c, pol);
    }

    // Phase 2: interpolate + evict-first stores (coalesced STG.32).
    #pragma unroll
    for (int k = 0; k < OUT_PER_THR; k++) {
        float v = (1.0f - w[k]) * a[k] + w[k] * b[k];
        __stcs(out + i0 + k * THREADS, v);
    }
}

extern "C" void kernel_launch(void* const* d_in, const int* in_sizes, int n_in,
                              void* d_out, int out_size) {
    const float* audio   = (const float*)d_in[0];
    const int*   p_crop  = (const int*)d_in[1];
    const int*   p_start = (const int*)d_in[2];
    float*       out     = (float*)d_out;

    const int n         = out_size;              // 2^25 (multiple of OUT_TILE)
    const int audio_len = in_sizes[0];
    const int blocks    = (n + OUT_TILE - 1) / OUT_TILE;   // 8192

    resample_pfd_kernel<<<blocks, THREADS>>>(audio, p_crop, p_start, out, n, audio_len);
}

// round 16
// speedup vs baseline: 1.0156x; 1.0156x over previous
#include <cuda_runtime.h>
#include <cuda_bf16.h>

// RandomResizedCrop resample: out[i] = (1-w)*cropped[lo_c] + w*cropped[hi_c],
// idx = f32(i) * delta, delta = f32(crop_len-1)/f32(n-1) (= 0.875f here),
// lo_c/hi_c clamped to crop_len-1 (JAX gather clamp), w from UNclamped
// floor(idx). Matches reference to rel_err 6.9e-9.
//
// Final shape (R13 optimum): 512-thread blocks, lane-consecutive gathers
// (each gather LDG spans ~1-2 lines), 8 outputs/thread with all 16 gathers
// issued before use (MLP~16), __stcs evict-first stores, and a single L2
// prefetch stream one resident-set ahead (PF_AHEAD=592) that decouples the
// DRAM read feed from gather consumption (the R11 win: DRAM 63% -> 72%).
// Characterized plateau: 202 MB/replay at ~5.7 TB/s mixed-stream DRAM rate;
// policy (R9/R10/R14), distance (R15), duplication (R12), MLP (R7), and
// occupancy knobs are all exhausted/flat.
// This round is subtractive: plain __ldg (demand-load policy proven inert;
// drops the 64-bit policy operand + per-block createpolicy) and prefetches
// spread 7-per-warp across all 16 warps instead of front-loaded in warps 0-3.

#define THREADS      512
#define OUT_PER_THR  8
#define OUT_TILE     (THREADS * OUT_PER_THR)   // 4096 outputs per block
#define PF_AHEAD     592                       // one resident set (4 x 148)
#define PF_PER_WARP  7                         // 16 warps x 7 = 112 lines
#define PF_LINES     112                       // 4096*0.875 floats = 112 x 128B
#define WIN_FLOATS   3584                      // OUT_TILE * 7/8

__global__ __launch_bounds__(THREADS)
void resample_final_kernel(const float* __restrict__ audio,
                           const int* __restrict__ p_crop,
                           const int* __restrict__ p_start,
                           float* __restrict__ out,
                           int n, int audio_len) {
    const int crop_len = __ldg(p_crop);
    const int start    = __ldg(p_start);
    const float delta  = (float)(crop_len - 1) / (float)(n - 1);
    const int clampv   = crop_len - 1;
    const float* __restrict__ base = audio + start;

    // Prefetch the input window of block (blk + PF_AHEAD): 112 lines of
    // 128 B, 7 lines per warp (lane < 7) so prefetch issue is spread across
    // all warps and overlaps each warp's own gather phase.
    {
        const int warp = threadIdx.x >> 5;
        const int lane = threadIdx.x & 31;
        if (lane < PF_PER_WARP) {
            int line = warp * PF_PER_WARP + lane;        // 0..111
            int b2   = blockIdx.x + PF_AHEAD;
            int pfi  = b2 * WIN_FLOATS + line * 32 - 8;  // -8: fp32 slack
            pfi = max(pfi, 0);
            pfi = min(start + pfi, audio_len - 1);
            asm volatile("prefetch.global.L2 [%0];" :: "l"(audio + pfi));
        }
    }

    const int i0 = blockIdx.x * OUT_TILE + threadIdx.x;

    // Phase 1: indices/weights, issue all 16 gathers (independent, MLP~16).
    float a[OUT_PER_THR], b[OUT_PER_THR], w[OUT_PER_THR];
    #pragma unroll
    for (int k = 0; k < OUT_PER_THR; k++) {
        int i      = i0 + k * THREADS;
        float fi   = (float)i;         // RN convert (matches f32 iota rounding)
        float idx  = fi * delta;       // RN multiply (matches XLA linspace)
        int lo     = (int)floorf(idx);
        w[k]       = idx - (float)lo;  // from UNclamped lo (reference semantics)
        int lo_c   = min(lo,     clampv);   // JAX gather clamp
        int hi_c   = min(lo + 1, clampv);
        a[k]       = __ldg(base + lo_c);
        b[k]       = __ldg(base + hi_c);
    }

    // Phase 2: interpolate + evict-first stores (coalesced STG.32).
    #pragma unroll
    for (int k = 0; k < OUT_PER_THR; k++) {
        float v = (1.0f - w[k]) * a[k] + w[k] * b[k];
        __stcs(out + i0 + k * THREADS, v);
    }
}

extern "C" void kernel_launch(void* const* d_in, const int* in_sizes, int n_in,
                              void* d_out, int out_size) {
    const float* audio   = (const float*)d_in[0];
    const int*   p_crop  = (const int*)d_in[1];
    const int*   p_start = (const int*)d_in[2];
    float*       out     = (float*)d_out;

    const int n         = out_size;              // 2^25 (multiple of OUT_TILE)
    const int audio_len = in_sizes[0];
    const int blocks    = (n + OUT_TILE - 1) / OUT_TILE;   // 8192

    resample_final_kernel<<<blocks, THREADS>>>(audio, p_crop, p_start, out, n, audio_len);
}

// round 17
// speedup vs baseline: 1.0163x; 1.0007x over previous
#include <cuda_runtime.h>
#include <cuda_bf16.h>

// RandomResizedCrop resample: out[i] = (1-w)*cropped[lo_c] + w*cropped[hi_c],
// idx = f32(i) * delta, delta = f32(crop_len-1)/f32(n-1) (= 0.875f here),
// lo_c/hi_c clamped to crop_len-1 (JAX gather clamp), w from UNclamped
// floor(idx). Matches reference to rel_err 6.9e-9.
//
// R13 read side unchanged (lane-consecutive gathers MLP~16, single L2
// prefetch stream one resident-set ahead). NEW: write side goes through
// SMEM + one cp.async.bulk (TMA S2G) 16 KB burst per block, replacing
// 1024 per-warp 128B store wavefronts. Hypothesis: the ~72% DRAM-active
// plateau is read/write turnaround from fine-grained write interleaving;
// coarse 16 KB write bursts cut turnarounds at each L2/DRAM partition.

#define THREADS      512
#define OUT_PER_THR  8
#define OUT_TILE     (THREADS * OUT_PER_THR)   // 4096 outputs per block
#define TILE_BYTES   (OUT_TILE * 4)            // 16 KB
#define PF_AHEAD     592                       // one resident set (4 x 148)
#define PF_PER_WARP  7                         // 16 warps x 7 = 112 lines
#define WIN_FLOATS   3584                      // OUT_TILE * 7/8

__global__ __launch_bounds__(THREADS)
void resample_bulk_kernel(const float* __restrict__ audio,
                          const int* __restrict__ p_crop,
                          const int* __restrict__ p_start,
                          float* __restrict__ out,
                          int n, int audio_len) {
    __shared__ __align__(128) float s[OUT_TILE];

    const int crop_len = __ldg(p_crop);
    const int start    = __ldg(p_start);
    const float delta  = (float)(crop_len - 1) / (float)(n - 1);
    const int clampv   = crop_len - 1;
    const float* __restrict__ base = audio + start;

    // Prefetch input window of block (blk + PF_AHEAD): 112 lines, 7/warp.
    {
        const int warp = threadIdx.x >> 5;
        const int lane = threadIdx.x & 31;
        if (lane < PF_PER_WARP) {
            int line = warp * PF_PER_WARP + lane;        // 0..111
            int b2   = blockIdx.x + PF_AHEAD;
            int pfi  = b2 * WIN_FLOATS + line * 32 - 8;  // -8: fp32 slack
            pfi = max(pfi, 0);
            pfi = min(start + pfi, audio_len - 1);
            asm volatile("prefetch.global.L2 [%0];" :: "l"(audio + pfi));
        }
    }

    const int o_base = blockIdx.x * OUT_TILE;
    const int i0 = o_base + threadIdx.x;

    // Phase 1: indices/weights, issue all 16 gathers (independent, MLP~16).
    float a[OUT_PER_THR], b[OUT_PER_THR], w[OUT_PER_THR];
    #pragma unroll
    for (int k = 0; k < OUT_PER_THR; k++) {
        int i      = i0 + k * THREADS;
        float fi   = (float)i;         // RN convert (matches f32 iota rounding)
        float idx  = fi * delta;       // RN multiply (matches XLA linspace)
        int lo     = (int)floorf(idx);
        w[k]       = idx - (float)lo;  // from UNclamped lo (reference semantics)
        int lo_c   = min(lo,     clampv);   // JAX gather clamp
        int hi_c   = min(lo + 1, clampv);
        a[k]       = __ldg(base + lo_c);
        b[k]       = __ldg(base + hi_c);
    }

    // Phase 2: interpolate into SMEM (layout == output layout of this tile).
    #pragma unroll
    for (int k = 0; k < OUT_PER_THR; k++) {
        s[threadIdx.x + k * THREADS] = (1.0f - w[k]) * a[k] + w[k] * b[k];
    }
    __syncthreads();

    // Phase 3: one 16 KB bulk store (TMA S2G) — coarse write burst.
    if (threadIdx.x == 0) {
        unsigned int s_addr;
        asm("{ .reg .u64 t; cvta.to.shared.u64 t, %1; cvt.u32.u64 %0, t; }"
            : "=r"(s_addr) : "l"(s));
        asm volatile("fence.proxy.async.shared::cta;" ::: "memory");
        asm volatile(
            "cp.async.bulk.global.shared::cta.bulk_group [%0], [%1], %2;"
            :: "l"(out + o_base), "r"(s_addr), "n"(TILE_BYTES)
            : "memory");
        asm volatile("cp.async.bulk.commit_group;" ::: "memory");
        asm volatile("cp.async.bulk.wait_group 0;" ::: "memory");
    }
}

extern "C" void kernel_launch(void* const* d_in, const int* in_sizes, int n_in,
                              void* d_out, int out_size) {
    const float* audio   = (const float*)d_in[0];
    const int*   p_crop  = (const int*)d_in[1];
    const int*   p_start = (const int*)d_in[2];
    float*       out     = (float*)d_out;

    const int n         = out_size;              // 2^25 (multiple of OUT_TILE)
    const int audio_len = in_sizes[0];
    const int blocks    = (n + OUT_TILE - 1) / OUT_TILE;   // 8192

    resample_bulk_kernel<<<blocks, THREADS>>>(audio, p_crop, p_start, out, n, audio_len);
}